// round 7
// baseline (speedup 1.0000x reference)
#include <cuda_runtime.h>

// EPN_layer: antisymmetric pairwise-MLP charge update.
// B=8, N=256, DH=32, DX=3, DQ=1, DE=8, H1=H2=32, DIN=80.
//
// Factorization (layer1 splits by input blocks):
//   A*[a] = inp_atom[a] @ W1[0:36] + b1,  Bt[a] = inp_atom[a] @ W1[36:72]
//   E[i,j] = e[i,j] @ W1[72:80]   (shared by both directions)
//   z1_ij = relu(A*_i + Bt_j + E), z1_ji = relu(A*_j + Bt_i + E); b3 cancels.
//
// R6 changes vs R5 (which was smem-crossbar-bound: LDS.128 = 2 wavefronts,
// so the 5KB/thread weight stream cost ~640 wf/thread):
//  * ALL weight reads (W2, W1c, b2, W3) go through uniform-address __ldg:
//    32 lanes @ same 16B -> 1 sector -> ~1 L1 wavefront per LDG.128, and the
//    ~6KB weight set is L1-resident. No smem weight staging, no pre-sync.
//  * per-atom table repacked as float4 k-pairs (A_k0,B_k0,A_k1,B_k1):
//    16 LDG.128/thread instead of 32 LDG.64.
//  * i-row A/B values read as uniform __ldg float4 (sAi/sBi smem removed).

#define BB 8
#define NN 256
#define H1C 32
#define H2C 32
#define DEC 8
#define NATOMS (BB * NN)   // 2048

// Per-atom projections packed by k-pair: g_AB4[kk*NATOMS+atom] =
//   (A[2kk], Bt[2kk], A[2kk+1], Bt[2kk+1])
__device__ float4 g_AB4[(H1C / 2) * NATOMS];

typedef unsigned long long u64;

__device__ __forceinline__ u64 dup2(float w) {
    u64 r; asm("mov.b64 %0, {%1, %1};" : "=l"(r) : "f"(w)); return r;
}
__device__ __forceinline__ void upk2(float& lo, float& hi, u64 v) {
    asm("mov.b64 {%0, %1}, %2;" : "=f"(lo), "=f"(hi) : "l"(v));
}
__device__ __forceinline__ u64 fma2(u64 a, u64 b, u64 c) {
    u64 d; asm("fma.rn.f32x2 %0, %1, %2, %3;" : "=l"(d) : "l"(a), "l"(b), "l"(c));
    return d;
}
// 16B read-only load returned as two u64 halves (uniform-address weight reads).
__device__ __forceinline__ ulonglong2 ldg128(const float* p) {
    longlong2 v = __ldg(reinterpret_cast<const longlong2*>(p));
    ulonglong2 r; r.x = (u64)v.x; r.y = (u64)v.y; return r;
}

// ---------------------------------------------------------------------------
// Phase 0: per-atom projections. Thread = (atom, k-pair): computes A*,Bt for
// k0=2kk and k1=2kk+1 and stores one float4.
// ---------------------------------------------------------------------------
__global__ void atom_proj_kernel(const float* __restrict__ h,
                                 const float* __restrict__ x,
                                 const float* __restrict__ q,
                                 const float* __restrict__ W1,
                                 const float* __restrict__ b1)
{
    int id = blockIdx.x * blockDim.x + threadIdx.x;   // atom*16 + kk
    if (id >= NATOMS * (H1C / 2)) return;
    int kk   = id & 15;
    int atom = id >> 4;
    int k0 = 2 * kk, k1 = k0 + 1;

    float a0 = b1[k0], a1 = b1[k1];
    float t0 = 0.0f,   t1 = 0.0f;
    #pragma unroll
    for (int f = 0; f < 3; ++f) {
        float xv = x[atom * 3 + f];
        a0 = fmaf(xv, W1[f * H1C + k0],        a0);
        a1 = fmaf(xv, W1[f * H1C + k1],        a1);
        t0 = fmaf(xv, W1[(36 + f) * H1C + k0], t0);
        t1 = fmaf(xv, W1[(36 + f) * H1C + k1], t1);
    }
    #pragma unroll
    for (int f = 0; f < 32; ++f) {
        float hv = h[atom * 32 + f];
        a0 = fmaf(hv, W1[(3 + f) * H1C + k0],  a0);
        a1 = fmaf(hv, W1[(3 + f) * H1C + k1],  a1);
        t0 = fmaf(hv, W1[(39 + f) * H1C + k0], t0);
        t1 = fmaf(hv, W1[(39 + f) * H1C + k1], t1);
    }
    float qv = q[atom];
    a0 = fmaf(qv, W1[35 * H1C + k0], a0);
    a1 = fmaf(qv, W1[35 * H1C + k1], a1);
    t0 = fmaf(qv, W1[71 * H1C + k0], t0);
    t1 = fmaf(qv, W1[71 * H1C + k1], t1);

    g_AB4[kk * NATOMS + atom] = make_float4(a0, t0, a1, t1);
}

// ---------------------------------------------------------------------------
// Phase 1: pair kernel. Block = (b,i); thread = j.
// ---------------------------------------------------------------------------
__global__ __launch_bounds__(256, 2)
void pair_kernel(const float* __restrict__ e,
                 const float* __restrict__ mask,
                 const float* __restrict__ q,
                 const float* __restrict__ W1,
                 const float* __restrict__ W2,
                 const float* __restrict__ b2,
                 const float* __restrict__ W3,
                 float* __restrict__ out)
{
    __shared__ float sred[8];

    const int bi = blockIdx.x;             // b*256 + i
    const int j  = threadIdx.x;
    const int atomBase = bi & ~(NN - 1);   // b*256

    // --- per-pair inputs ---
    const float4* ep = reinterpret_cast<const float4*>(e + ((size_t)bi * NN + j) * DEC);
    float4 e0 = ep[0], e1 = ep[1];
    float ev[8] = {e0.x, e0.y, e0.z, e0.w, e1.x, e1.y, e1.z, e1.w};

    float emax = ev[0];
    #pragma unroll
    for (int m = 1; m < 8; ++m) emax = fmaxf(emax, ev[m]);
    const float mval  = mask[(size_t)bi * NN + j];
    const float scale = (emax > 1e-5f) ? 0.5f * mval : 0.0f;

    // --- E = e @ W1c, packed over consecutive k-pairs (uniform LDG.128) ---
    u64 Epk[H1C / 2];
    #pragma unroll
    for (int kk = 0; kk < 16; ++kk) Epk[kk] = 0ull;
    #pragma unroll
    for (int m = 0; m < 8; ++m) {
        u64 em2 = dup2(ev[m]);
        const float* wrow = W1 + (72 + m) * H1C;
        #pragma unroll
        for (int f4 = 0; f4 < 8; ++f4) {
            ulonglong2 w = ldg128(wrow + 4 * f4);   // 1-wf uniform load
            Epk[2 * f4]     = fma2(em2, w.x, Epk[2 * f4]);
            Epk[2 * f4 + 1] = fma2(em2, w.y, Epk[2 * f4 + 1]);
        }
    }

    // --- z1 both directions (uniform i-row float4 + coalesced j float4) ---
    const float4* __restrict__ AB4 = g_AB4;
    float z_ij[H1C], z_ji[H1C];
    #pragma unroll
    for (int kk = 0; kk < 16; ++kk) {
        int k0 = 2 * kk;
        float E0, E1; upk2(E0, E1, Epk[kk]);
        float4 abi = __ldg(&AB4[kk * NATOMS + bi]);            // uniform, L1-hit
        float4 abj = __ldg(&AB4[kk * NATOMS + atomBase + j]);  // coalesced
        z_ij[k0]     = fmaxf(abi.x + abj.y + E0, 0.0f);
        z_ji[k0]     = fmaxf(abj.x + abi.y + E0, 0.0f);
        z_ij[k0 + 1] = fmaxf(abi.z + abj.w + E1, 0.0f);
        z_ji[k0 + 1] = fmaxf(abj.z + abi.w + E1, 0.0f);
    }

    // --- layers 2+3: k in two halves; both directions share every uniform
    //     W2 row load; weights never touch shared memory ---
    float s_ij = 0.0f, s_ji = 0.0f;
    #pragma unroll
    for (int half = 0; half < 2; ++half) {
        u64 accI[8], accJ[8];
        const long long* b2p = reinterpret_cast<const long long*>(b2) + half * 8;
        #pragma unroll
        for (int kk = 0; kk < 8; ++kk) {
            u64 bv = (u64)__ldg(&b2p[kk]);
            accI[kk] = bv; accJ[kk] = bv;
        }

        #pragma unroll
        for (int m = 0; m < H1C; ++m) {
            const float* wrow = W2 + m * H2C + half * 16;
            u64 zi2 = dup2(z_ij[m]);
            u64 zj2 = dup2(z_ji[m]);
            #pragma unroll
            for (int f4 = 0; f4 < 4; ++f4) {
                ulonglong2 w = ldg128(wrow + 4 * f4);   // 4 consecutive W2[m][k]
                accI[2 * f4]     = fma2(zi2, w.x, accI[2 * f4]);
                accJ[2 * f4]     = fma2(zj2, w.x, accJ[2 * f4]);
                accI[2 * f4 + 1] = fma2(zi2, w.y, accI[2 * f4 + 1]);
                accJ[2 * f4 + 1] = fma2(zj2, w.y, accJ[2 * f4 + 1]);
            }
        }
        #pragma unroll
        for (int kk = 0; kk < 8; ++kk) {
            int k0 = half * 16 + 2 * kk;
            float w30 = __ldg(&W3[k0]);
            float w31 = __ldg(&W3[k0 + 1]);
            float t0, t1; upk2(t0, t1, accI[kk]);
            float u0, u1; upk2(u0, u1, accJ[kk]);
            s_ij = fmaf(fmaxf(t0, 0.0f), w30, s_ij);
            s_ij = fmaf(fmaxf(t1, 0.0f), w31, s_ij);
            s_ji = fmaf(fmaxf(u0, 0.0f), w30, s_ji);
            s_ji = fmaf(fmaxf(u1, 0.0f), w31, s_ji);
        }
    }
    float val = scale * (s_ij - s_ji);   // b3 cancels

    // --- block reduction over j ---
    #pragma unroll
    for (int off = 16; off > 0; off >>= 1)
        val += __shfl_xor_sync(0xffffffffu, val, off);
    if ((threadIdx.x & 31) == 0) sred[threadIdx.x >> 5] = val;
    __syncthreads();
    if (threadIdx.x == 0) {
        float t = 0.0f;
        #pragma unroll
        for (int w = 0; w < 8; ++w) t += sred[w];
        out[bi] = q[bi] + t;
    }
}

// ---------------------------------------------------------------------------
// Launch. Inputs (metadata order): h, e, x, q, mask, W1, b1, W2, b2, W3, b3.
// ---------------------------------------------------------------------------
extern "C" void kernel_launch(void* const* d_in, const int* in_sizes, int n_in,
                              void* d_out, int out_size)
{
    const float* h    = (const float*)d_in[0];
    const float* e    = (const float*)d_in[1];
    const float* x    = (const float*)d_in[2];
    const float* q    = (const float*)d_in[3];
    const float* mask = (const float*)d_in[4];
    const float* W1   = (const float*)d_in[5];
    const float* b1   = (const float*)d_in[6];
    const float* W2   = (const float*)d_in[7];
    const float* b2   = (const float*)d_in[8];
    const float* W3   = (const float*)d_in[9];
    // d_in[10] = b3: cancels in elec_ij - elec_ji.
    float* out = (float*)d_out;

    atom_proj_kernel<<<(NATOMS * (H1C / 2) + 255) / 256, 256>>>(h, x, q, W1, b1);
    pair_kernel<<<NATOMS, 256>>>(e, mask, q, W1, W2, b2, W3, out);
}

// round 8
// speedup vs baseline: 1.3308x; 1.3308x over previous
#include <cuda_runtime.h>

// EPN_layer: antisymmetric pairwise-MLP charge update.
// B=8, N=256, DH=32, DX=3, DQ=1, DE=8, H1=H2=32, DIN=80.
//
// Factorization (layer1 splits by input blocks):
//   A*[a] = inp_atom[a] @ W1[0:36] + b1,  Bt[a] = inp_atom[a] @ W1[36:72]
//   E[i,j] = e[i,j] @ W1[72:80]   (shared by both directions)
//   z1_ij = relu(A*_i + Bt_j + E), z1_ji = relu(A*_j + Bt_i + E); b3 cancels.
//
// R7: revert R6's LDG-weight experiment (regressed: LDG tag/issue cost > LDS).
// Back to smem weights (R5) + G=2 amortization: block = TWO i-rows (2r, 2r+1),
// thread j evaluates 4 MLPs (2 pairs x 2 dirs) so every W2/W1c shared-memory
// load is amortized over 4 evals instead of 2. k split in halves (acc fits),
// E computed per 16-m chunk into registers (recomputed per k-half), z streamed
// per m (never materialized).

#define BB 8
#define NN 256
#define H1C 32
#define H2C 32
#define DEC 8
#define NATOMS (BB * NN)   // 2048

// Per-atom projections packed by k-pair: g_AB4[kk*NATOMS+atom] =
//   (A[2kk], Bt[2kk], A[2kk+1], Bt[2kk+1])
__device__ float4 g_AB4[(H1C / 2) * NATOMS];

typedef unsigned long long u64;

__device__ __forceinline__ u64 dup2(float w) {
    u64 r; asm("mov.b64 %0, {%1, %1};" : "=l"(r) : "f"(w)); return r;
}
__device__ __forceinline__ u64 pk2(float lo, float hi) {
    u64 r; asm("mov.b64 %0, {%1, %2};" : "=l"(r) : "f"(lo), "f"(hi)); return r;
}
__device__ __forceinline__ void upk2(float& lo, float& hi, u64 v) {
    asm("mov.b64 {%0, %1}, %2;" : "=f"(lo), "=f"(hi) : "l"(v));
}
__device__ __forceinline__ u64 fma2(u64 a, u64 b, u64 c) {
    u64 d; asm("fma.rn.f32x2 %0, %1, %2, %3;" : "=l"(d) : "l"(a), "l"(b), "l"(c));
    return d;
}
__device__ __forceinline__ u64 add2(u64 a, u64 b) {
    u64 d; asm("add.rn.f32x2 %0, %1, %2;" : "=l"(d) : "l"(a), "l"(b));
    return d;
}

// ---------------------------------------------------------------------------
// Phase 0: per-atom projections. Thread = (atom, k-pair).
// ---------------------------------------------------------------------------
__global__ void atom_proj_kernel(const float* __restrict__ h,
                                 const float* __restrict__ x,
                                 const float* __restrict__ q,
                                 const float* __restrict__ W1,
                                 const float* __restrict__ b1)
{
    int id = blockIdx.x * blockDim.x + threadIdx.x;   // atom*16 + kk
    if (id >= NATOMS * (H1C / 2)) return;
    int kk   = id & 15;
    int atom = id >> 4;
    int k0 = 2 * kk, k1 = k0 + 1;

    float a0 = b1[k0], a1 = b1[k1];
    float t0 = 0.0f,   t1 = 0.0f;
    #pragma unroll
    for (int f = 0; f < 3; ++f) {
        float xv = x[atom * 3 + f];
        a0 = fmaf(xv, W1[f * H1C + k0],        a0);
        a1 = fmaf(xv, W1[f * H1C + k1],        a1);
        t0 = fmaf(xv, W1[(36 + f) * H1C + k0], t0);
        t1 = fmaf(xv, W1[(36 + f) * H1C + k1], t1);
    }
    #pragma unroll
    for (int f = 0; f < 32; ++f) {
        float hv = h[atom * 32 + f];
        a0 = fmaf(hv, W1[(3 + f) * H1C + k0],  a0);
        a1 = fmaf(hv, W1[(3 + f) * H1C + k1],  a1);
        t0 = fmaf(hv, W1[(39 + f) * H1C + k0], t0);
        t1 = fmaf(hv, W1[(39 + f) * H1C + k1], t1);
    }
    float qv = q[atom];
    a0 = fmaf(qv, W1[35 * H1C + k0], a0);
    a1 = fmaf(qv, W1[35 * H1C + k1], a1);
    t0 = fmaf(qv, W1[71 * H1C + k0], t0);
    t1 = fmaf(qv, W1[71 * H1C + k1], t1);

    g_AB4[kk * NATOMS + atom] = make_float4(a0, t0, a1, t1);
}

// ---------------------------------------------------------------------------
// Phase 1: pair kernel. Block = rows (2r, 2r+1); thread = j; 4 MLP evals.
// ---------------------------------------------------------------------------
__global__ __launch_bounds__(256, 2)
void pair_kernel(const float* __restrict__ e,
                 const float* __restrict__ mask,
                 const float* __restrict__ q,
                 const float* __restrict__ W1,
                 const float* __restrict__ W2,
                 const float* __restrict__ b2,
                 const float* __restrict__ W3,
                 float* __restrict__ out)
{
    __shared__ alignas(16) float  sW2[H1C][H2C];   // raw W2 [m][k]
    __shared__ alignas(16) float  sW1c[DEC][H1C];  // e-projection rows, m-contig
    __shared__ alignas(16) float4 sIT[H1C];        // (Ai0, Ai1, Bi0, Bi1) per m
    __shared__ alignas(16) float  sB2[H2C];
    __shared__ float sW3[H2C];
    __shared__ float sred[2][8];

    const int r   = blockIdx.x;            // 0..1023
    const int bi0 = 2 * r;                 // global row b*256 + i0
    const int bi1 = bi0 + 1;
    const int j   = threadIdx.x;
    const int base = bi0 & ~(NN - 1);      // b*256

    // ---- cooperative staging ----
    #pragma unroll
    for (int t = 0; t < 4; ++t) {
        int idx = threadIdx.x + t * 256;   // 1024 = 32x32
        sW2[idx >> 5][idx & 31] = W2[idx];
    }
    if (threadIdx.x < DEC * H1C)
        sW1c[threadIdx.x >> 5][threadIdx.x & 31] = W1[72 * H1C + threadIdx.x];
    if (threadIdx.x < H2C) {
        int m = threadIdx.x;
        sB2[m] = b2[m];
        sW3[m] = W3[m];
        float4 f0 = g_AB4[(m >> 1) * NATOMS + bi0];
        float4 f1 = g_AB4[(m >> 1) * NATOMS + bi1];
        float A0 = (m & 1) ? f0.z : f0.x, B0 = (m & 1) ? f0.w : f0.y;
        float A1 = (m & 1) ? f1.z : f1.x, B1 = (m & 1) ? f1.w : f1.y;
        sIT[m] = make_float4(A0, A1, B0, B1);
    }
    __syncthreads();

    // ---- scale factors for both pairs ----
    const float4* ep0 = reinterpret_cast<const float4*>(e + ((size_t)bi0 * NN + j) * DEC);
    const float4* ep1 = reinterpret_cast<const float4*>(e + ((size_t)bi1 * NN + j) * DEC);
    float scale0, scale1;
    {
        float4 a = ep0[0], b = ep0[1];
        float mx = fmaxf(fmaxf(fmaxf(a.x, a.y), fmaxf(a.z, a.w)),
                         fmaxf(fmaxf(b.x, b.y), fmaxf(b.z, b.w)));
        scale0 = (mx > 1e-5f) ? 0.5f * mask[(size_t)bi0 * NN + j] : 0.0f;
        float4 c = ep1[0], d = ep1[1];
        float my = fmaxf(fmaxf(fmaxf(c.x, c.y), fmaxf(c.z, c.w)),
                         fmaxf(fmaxf(d.x, d.y), fmaxf(d.z, d.w)));
        scale1 = (my > 1e-5f) ? 0.5f * mask[(size_t)bi1 * NN + j] : 0.0f;
    }

    // s[0]=ij(i0) s[1]=ji(i0) s[2]=ij(i1) s[3]=ji(i1)
    float s0 = 0.0f, s1 = 0.0f, s2 = 0.0f, s3 = 0.0f;

    #pragma unroll
    for (int kh = 0; kh < 2; ++kh) {
        // accumulators: 4 evals x 8 k-pairs (k = kh*16 .. kh*16+15)
        u64 acc0[8], acc1[8], acc2[8], acc3[8];
        const u64* b2p = reinterpret_cast<const u64*>(&sB2[kh * 16]);
        #pragma unroll
        for (int kk = 0; kk < 8; ++kk) {
            u64 bv = b2p[kk];
            acc0[kk] = bv; acc1[kk] = bv; acc2[kk] = bv; acc3[kk] = bv;
        }

        #pragma unroll
        for (int mc = 0; mc < 2; ++mc) {
            // E for m-chunk [mc*16, mc*16+16), both pairs, packed by m-pair.
            u64 Em0[8], Em1[8];
            #pragma unroll
            for (int mm = 0; mm < 8; ++mm) { Em0[mm] = 0ull; Em1[mm] = 0ull; }
            {
                // reload e (L1-hit) to keep register pressure down
                float4 a = __ldg(ep0), b = __ldg(ep0 + 1);
                float4 c = __ldg(ep1), d = __ldg(ep1 + 1);
                float ev0[8] = {a.x, a.y, a.z, a.w, b.x, b.y, b.z, b.w};
                float ev1[8] = {c.x, c.y, c.z, c.w, d.x, d.y, d.z, d.w};
                #pragma unroll
                for (int f = 0; f < 8; ++f) {
                    const u64* wr = reinterpret_cast<const u64*>(&sW1c[f][mc * 16]);
                    u64 d0 = dup2(ev0[f]);
                    u64 d1 = dup2(ev1[f]);
                    #pragma unroll
                    for (int mm = 0; mm < 8; ++mm) {
                        u64 w = wr[mm];
                        Em0[mm] = fma2(d0, w, Em0[mm]);
                        Em1[mm] = fma2(d1, w, Em1[mm]);
                    }
                }
            }

            // m loop over the chunk, two m per iteration (abj float4 covers 2)
            #pragma unroll
            for (int mm = 0; mm < 8; ++mm) {
                float4 ab = __ldg(&g_AB4[(mc * 8 + mm) * NATOMS + base + j]);
                float E0a, E0b; upk2(E0a, E0b, Em0[mm]);   // pair0: E[m], E[m+1]
                float E1a, E1b; upk2(E1a, E1b, Em1[mm]);   // pair1

                #pragma unroll
                for (int half = 0; half < 2; ++half) {
                    int m = mc * 16 + 2 * mm + half;
                    float Aj = half ? ab.z : ab.x;
                    float Bj = half ? ab.w : ab.y;
                    u64 Ep = half ? pk2(E0b, E1b) : pk2(E0a, E1a);
                    float4 it = sIT[m];                    // Ai0,Ai1,Bi0,Bi1
                    u64 tI = add2(add2(pk2(it.x, it.y), dup2(Bj)), Ep);
                    u64 tJ = add2(add2(pk2(it.z, it.w), dup2(Aj)), Ep);
                    float zi0, zi1; upk2(zi0, zi1, tI);
                    float zj0, zj1; upk2(zj0, zj1, tJ);
                    u64 d0i = dup2(fmaxf(zi0, 0.0f));
                    u64 d0j = dup2(fmaxf(zj0, 0.0f));
                    u64 d1i = dup2(fmaxf(zi1, 0.0f));
                    u64 d1j = dup2(fmaxf(zj1, 0.0f));

                    const ulonglong2* wr =
                        reinterpret_cast<const ulonglong2*>(&sW2[m][kh * 16]);
                    #pragma unroll
                    for (int t = 0; t < 4; ++t) {
                        ulonglong2 w = wr[t];              // 4 consecutive W2[m][k]
                        acc0[2 * t]     = fma2(d0i, w.x, acc0[2 * t]);
                        acc1[2 * t]     = fma2(d0j, w.x, acc1[2 * t]);
                        acc2[2 * t]     = fma2(d1i, w.x, acc2[2 * t]);
                        acc3[2 * t]     = fma2(d1j, w.x, acc3[2 * t]);
                        acc0[2 * t + 1] = fma2(d0i, w.y, acc0[2 * t + 1]);
                        acc1[2 * t + 1] = fma2(d0j, w.y, acc1[2 * t + 1]);
                        acc2[2 * t + 1] = fma2(d1i, w.y, acc2[2 * t + 1]);
                        acc3[2 * t + 1] = fma2(d1j, w.y, acc3[2 * t + 1]);
                    }
                }
            }
        }

        // epilogue for this k-half: relu + W3 dot
        #pragma unroll
        for (int kk = 0; kk < 8; ++kk) {
            int k0 = kh * 16 + 2 * kk;
            float w0 = sW3[k0], w1 = sW3[k0 + 1];
            float a, b;
            upk2(a, b, acc0[kk]);
            s0 = fmaf(fmaxf(a, 0.0f), w0, s0); s0 = fmaf(fmaxf(b, 0.0f), w1, s0);
            upk2(a, b, acc1[kk]);
            s1 = fmaf(fmaxf(a, 0.0f), w0, s1); s1 = fmaf(fmaxf(b, 0.0f), w1, s1);
            upk2(a, b, acc2[kk]);
            s2 = fmaf(fmaxf(a, 0.0f), w0, s2); s2 = fmaf(fmaxf(b, 0.0f), w1, s2);
            upk2(a, b, acc3[kk]);
            s3 = fmaf(fmaxf(a, 0.0f), w0, s3); s3 = fmaf(fmaxf(b, 0.0f), w1, s3);
        }
    }

    float val0 = scale0 * (s0 - s1);   // b3 cancels
    float val1 = scale1 * (s2 - s3);

    // ---- block reductions over j for both rows ----
    #pragma unroll
    for (int off = 16; off > 0; off >>= 1) {
        val0 += __shfl_xor_sync(0xffffffffu, val0, off);
        val1 += __shfl_xor_sync(0xffffffffu, val1, off);
    }
    if ((threadIdx.x & 31) == 0) {
        sred[0][threadIdx.x >> 5] = val0;
        sred[1][threadIdx.x >> 5] = val1;
    }
    __syncthreads();
    if (threadIdx.x == 0) {
        float t0 = 0.0f, t1 = 0.0f;
        #pragma unroll
        for (int w = 0; w < 8; ++w) { t0 += sred[0][w]; t1 += sred[1][w]; }
        out[bi0] = q[bi0] + t0;
        out[bi1] = q[bi1] + t1;
    }
}

// ---------------------------------------------------------------------------
// Launch. Inputs (metadata order): h, e, x, q, mask, W1, b1, W2, b2, W3, b3.
// ---------------------------------------------------------------------------
extern "C" void kernel_launch(void* const* d_in, const int* in_sizes, int n_in,
                              void* d_out, int out_size)
{
    const float* h    = (const float*)d_in[0];
    const float* e    = (const float*)d_in[1];
    const float* x    = (const float*)d_in[2];
    const float* q    = (const float*)d_in[3];
    const float* mask = (const float*)d_in[4];
    const float* W1   = (const float*)d_in[5];
    const float* b1   = (const float*)d_in[6];
    const float* W2   = (const float*)d_in[7];
    const float* b2   = (const float*)d_in[8];
    const float* W3   = (const float*)d_in[9];
    // d_in[10] = b3: cancels in elec_ij - elec_ji.
    float* out = (float*)d_out;

    atom_proj_kernel<<<(NATOMS * (H1C / 2) + 255) / 256, 256>>>(h, x, q, W1, b1);
    pair_kernel<<<NATOMS / 2, 256>>>(e, mask, q, W1, W2, b2, W3, out);
}

// round 9
// speedup vs baseline: 1.5300x; 1.1497x over previous
#include <cuda_runtime.h>

// EPN_layer: antisymmetric pairwise-MLP charge update.
// B=8, N=256, DH=32, DX=3, DQ=1, DE=8, H1=H2=32, DIN=80.
//
// Factorization (layer1 splits by input blocks):
//   A*[a] = inp_atom[a] @ W1[0:36] + b1,  Bt[a] = inp_atom[a] @ W1[36:72]
//   E[i,j] = e[i,j] @ W1[72:80]   (shared by both directions)
//   z1_ij = relu(A*_i + Bt_j + E), z1_ji = relu(A*_j + Bt_i + E); b3 cancels.
//
// R8 = R7 (G=2: block handles rows 2r,2r+1; thread j does 4 MLP evals so
// every W2/W1c smem load amortizes over 4 evals) with the register blowup
// fixed (R7 spilled: regs=128 cap, L2 25%, DRAM 6.5%):
//  * E computed in chunks of 4 m (Em live = 8 regs, was 32)
//  * e-values held resident (16 regs) instead of re-__ldg'ing float4s
//    inside every chunk (removes transient pressure spikes)

#define BB 8
#define NN 256
#define H1C 32
#define H2C 32
#define DEC 8
#define NATOMS (BB * NN)   // 2048

// Per-atom projections packed by k-pair: g_AB4[kk*NATOMS+atom] =
//   (A[2kk], Bt[2kk], A[2kk+1], Bt[2kk+1])
__device__ float4 g_AB4[(H1C / 2) * NATOMS];

typedef unsigned long long u64;

__device__ __forceinline__ u64 dup2(float w) {
    u64 r; asm("mov.b64 %0, {%1, %1};" : "=l"(r) : "f"(w)); return r;
}
__device__ __forceinline__ u64 pk2(float lo, float hi) {
    u64 r; asm("mov.b64 %0, {%1, %2};" : "=l"(r) : "f"(lo), "f"(hi)); return r;
}
__device__ __forceinline__ void upk2(float& lo, float& hi, u64 v) {
    asm("mov.b64 {%0, %1}, %2;" : "=f"(lo), "=f"(hi) : "l"(v));
}
__device__ __forceinline__ u64 fma2(u64 a, u64 b, u64 c) {
    u64 d; asm("fma.rn.f32x2 %0, %1, %2, %3;" : "=l"(d) : "l"(a), "l"(b), "l"(c));
    return d;
}
__device__ __forceinline__ u64 add2(u64 a, u64 b) {
    u64 d; asm("add.rn.f32x2 %0, %1, %2;" : "=l"(d) : "l"(a), "l"(b));
    return d;
}

// ---------------------------------------------------------------------------
// Phase 0: per-atom projections. Thread = (atom, k-pair).
// ---------------------------------------------------------------------------
__global__ void atom_proj_kernel(const float* __restrict__ h,
                                 const float* __restrict__ x,
                                 const float* __restrict__ q,
                                 const float* __restrict__ W1,
                                 const float* __restrict__ b1)
{
    int id = blockIdx.x * blockDim.x + threadIdx.x;   // atom*16 + kk
    if (id >= NATOMS * (H1C / 2)) return;
    int kk   = id & 15;
    int atom = id >> 4;
    int k0 = 2 * kk, k1 = k0 + 1;

    float a0 = b1[k0], a1 = b1[k1];
    float t0 = 0.0f,   t1 = 0.0f;
    #pragma unroll
    for (int f = 0; f < 3; ++f) {
        float xv = x[atom * 3 + f];
        a0 = fmaf(xv, W1[f * H1C + k0],        a0);
        a1 = fmaf(xv, W1[f * H1C + k1],        a1);
        t0 = fmaf(xv, W1[(36 + f) * H1C + k0], t0);
        t1 = fmaf(xv, W1[(36 + f) * H1C + k1], t1);
    }
    #pragma unroll
    for (int f = 0; f < 32; ++f) {
        float hv = h[atom * 32 + f];
        a0 = fmaf(hv, W1[(3 + f) * H1C + k0],  a0);
        a1 = fmaf(hv, W1[(3 + f) * H1C + k1],  a1);
        t0 = fmaf(hv, W1[(39 + f) * H1C + k0], t0);
        t1 = fmaf(hv, W1[(39 + f) * H1C + k1], t1);
    }
    float qv = q[atom];
    a0 = fmaf(qv, W1[35 * H1C + k0], a0);
    a1 = fmaf(qv, W1[35 * H1C + k1], a1);
    t0 = fmaf(qv, W1[71 * H1C + k0], t0);
    t1 = fmaf(qv, W1[71 * H1C + k1], t1);

    g_AB4[kk * NATOMS + atom] = make_float4(a0, t0, a1, t1);
}

// ---------------------------------------------------------------------------
// Phase 1: pair kernel. Block = rows (2r, 2r+1); thread = j; 4 MLP evals.
// ---------------------------------------------------------------------------
__global__ __launch_bounds__(256, 2)
void pair_kernel(const float* __restrict__ e,
                 const float* __restrict__ mask,
                 const float* __restrict__ q,
                 const float* __restrict__ W1,
                 const float* __restrict__ W2,
                 const float* __restrict__ b2,
                 const float* __restrict__ W3,
                 float* __restrict__ out)
{
    __shared__ alignas(16) float  sW2[H1C][H2C];   // raw W2 [m][k]
    __shared__ alignas(16) float  sW1c[DEC][H1C];  // e-projection rows [f][m]
    __shared__ alignas(16) float4 sIT[H1C];        // (Ai0, Ai1, Bi0, Bi1) per m
    __shared__ alignas(16) float  sB2[H2C];
    __shared__ float sW3[H2C];
    __shared__ float sred[2][8];

    const int r   = blockIdx.x;            // 0..1023
    const int bi0 = 2 * r;                 // global row b*256 + i0
    const int bi1 = bi0 + 1;
    const int j   = threadIdx.x;
    const int base = bi0 & ~(NN - 1);      // b*256

    // ---- cooperative staging ----
    #pragma unroll
    for (int t = 0; t < 4; ++t) {
        int idx = threadIdx.x + t * 256;   // 1024 = 32x32
        sW2[idx >> 5][idx & 31] = W2[idx];
    }
    if (threadIdx.x < DEC * H1C)
        sW1c[threadIdx.x >> 5][threadIdx.x & 31] = W1[72 * H1C + threadIdx.x];
    if (threadIdx.x < H2C) {
        int m = threadIdx.x;
        sB2[m] = b2[m];
        sW3[m] = W3[m];
        float4 f0 = g_AB4[(m >> 1) * NATOMS + bi0];
        float4 f1 = g_AB4[(m >> 1) * NATOMS + bi1];
        float A0 = (m & 1) ? f0.z : f0.x, B0 = (m & 1) ? f0.w : f0.y;
        float A1 = (m & 1) ? f1.z : f1.x, B1 = (m & 1) ? f1.w : f1.y;
        sIT[m] = make_float4(A0, A1, B0, B1);
    }
    __syncthreads();

    // ---- e rows (kept resident) + scale factors ----
    float ev0[8], ev1[8];
    {
        const float4* ep0 = reinterpret_cast<const float4*>(e + ((size_t)bi0 * NN + j) * DEC);
        const float4* ep1 = reinterpret_cast<const float4*>(e + ((size_t)bi1 * NN + j) * DEC);
        float4 a = ep0[0], b = ep0[1];
        float4 c = ep1[0], d = ep1[1];
        ev0[0]=a.x; ev0[1]=a.y; ev0[2]=a.z; ev0[3]=a.w;
        ev0[4]=b.x; ev0[5]=b.y; ev0[6]=b.z; ev0[7]=b.w;
        ev1[0]=c.x; ev1[1]=c.y; ev1[2]=c.z; ev1[3]=c.w;
        ev1[4]=d.x; ev1[5]=d.y; ev1[6]=d.z; ev1[7]=d.w;
    }
    float scale0, scale1;
    {
        float mx = ev0[0], my = ev1[0];
        #pragma unroll
        for (int f = 1; f < 8; ++f) { mx = fmaxf(mx, ev0[f]); my = fmaxf(my, ev1[f]); }
        scale0 = (mx > 1e-5f) ? 0.5f * mask[(size_t)bi0 * NN + j] : 0.0f;
        scale1 = (my > 1e-5f) ? 0.5f * mask[(size_t)bi1 * NN + j] : 0.0f;
    }

    // s0=ij(i0) s1=ji(i0) s2=ij(i1) s3=ji(i1)
    float s0 = 0.0f, s1 = 0.0f, s2 = 0.0f, s3 = 0.0f;

    #pragma unroll
    for (int kh = 0; kh < 2; ++kh) {
        // accumulators: 4 evals x 8 k-pairs (k = kh*16 .. kh*16+15)
        u64 acc0[8], acc1[8], acc2[8], acc3[8];
        const u64* b2p = reinterpret_cast<const u64*>(&sB2[kh * 16]);
        #pragma unroll
        for (int kk = 0; kk < 8; ++kk) {
            u64 bv = b2p[kk];
            acc0[kk] = bv; acc1[kk] = bv; acc2[kk] = bv; acc3[kk] = bv;
        }

        #pragma unroll
        for (int mc = 0; mc < 8; ++mc) {        // chunks of 4 m
            // E for m in [4mc, 4mc+4), both pairs, m-pair-packed (8 regs live)
            u64 Em0[2] = {0ull, 0ull};
            u64 Em1[2] = {0ull, 0ull};
            #pragma unroll
            for (int f = 0; f < 8; ++f) {
                const ulonglong2 w =
                    *reinterpret_cast<const ulonglong2*>(&sW1c[f][4 * mc]);
                u64 d0 = dup2(ev0[f]);
                u64 d1 = dup2(ev1[f]);
                Em0[0] = fma2(d0, w.x, Em0[0]);
                Em0[1] = fma2(d0, w.y, Em0[1]);
                Em1[0] = fma2(d1, w.x, Em1[0]);
                Em1[1] = fma2(d1, w.y, Em1[1]);
            }

            #pragma unroll
            for (int mm = 0; mm < 2; ++mm) {    // 2 m per float4 ab
                float4 ab = __ldg(&g_AB4[(2 * mc + mm) * NATOMS + base + j]);
                float E0a, E0b; upk2(E0a, E0b, Em0[mm]);   // pair0: E[m], E[m+1]
                float E1a, E1b; upk2(E1a, E1b, Em1[mm]);   // pair1

                #pragma unroll
                for (int half = 0; half < 2; ++half) {
                    int m = 4 * mc + 2 * mm + half;
                    float Aj = half ? ab.z : ab.x;
                    float Bj = half ? ab.w : ab.y;
                    u64 Ep = half ? pk2(E0b, E1b) : pk2(E0a, E1a);
                    float4 it = sIT[m];                    // Ai0,Ai1,Bi0,Bi1
                    u64 tI = add2(add2(pk2(it.x, it.y), dup2(Bj)), Ep);
                    u64 tJ = add2(add2(pk2(it.z, it.w), dup2(Aj)), Ep);
                    float zi0, zi1; upk2(zi0, zi1, tI);
                    float zj0, zj1; upk2(zj0, zj1, tJ);
                    u64 d0i = dup2(fmaxf(zi0, 0.0f));
                    u64 d0j = dup2(fmaxf(zj0, 0.0f));
                    u64 d1i = dup2(fmaxf(zi1, 0.0f));
                    u64 d1j = dup2(fmaxf(zj1, 0.0f));

                    const ulonglong2* wr =
                        reinterpret_cast<const ulonglong2*>(&sW2[m][kh * 16]);
                    #pragma unroll
                    for (int t = 0; t < 4; ++t) {
                        ulonglong2 w = wr[t];              // 4 consecutive W2[m][k]
                        acc0[2 * t]     = fma2(d0i, w.x, acc0[2 * t]);
                        acc1[2 * t]     = fma2(d0j, w.x, acc1[2 * t]);
                        acc2[2 * t]     = fma2(d1i, w.x, acc2[2 * t]);
                        acc3[2 * t]     = fma2(d1j, w.x, acc3[2 * t]);
                        acc0[2 * t + 1] = fma2(d0i, w.y, acc0[2 * t + 1]);
                        acc1[2 * t + 1] = fma2(d0j, w.y, acc1[2 * t + 1]);
                        acc2[2 * t + 1] = fma2(d1i, w.y, acc2[2 * t + 1]);
                        acc3[2 * t + 1] = fma2(d1j, w.y, acc3[2 * t + 1]);
                    }
                }
            }
        }

        // epilogue for this k-half: relu + W3 dot
        #pragma unroll
        for (int kk = 0; kk < 8; ++kk) {
            int k0 = kh * 16 + 2 * kk;
            float w0 = sW3[k0], w1 = sW3[k0 + 1];
            float a, b;
            upk2(a, b, acc0[kk]);
            s0 = fmaf(fmaxf(a, 0.0f), w0, s0); s0 = fmaf(fmaxf(b, 0.0f), w1, s0);
            upk2(a, b, acc1[kk]);
            s1 = fmaf(fmaxf(a, 0.0f), w0, s1); s1 = fmaf(fmaxf(b, 0.0f), w1, s1);
            upk2(a, b, acc2[kk]);
            s2 = fmaf(fmaxf(a, 0.0f), w0, s2); s2 = fmaf(fmaxf(b, 0.0f), w1, s2);
            upk2(a, b, acc3[kk]);
            s3 = fmaf(fmaxf(a, 0.0f), w0, s3); s3 = fmaf(fmaxf(b, 0.0f), w1, s3);
        }
    }

    float val0 = scale0 * (s0 - s1);   // b3 cancels
    float val1 = scale1 * (s2 - s3);

    // ---- block reductions over j for both rows ----
    #pragma unroll
    for (int off = 16; off > 0; off >>= 1) {
        val0 += __shfl_xor_sync(0xffffffffu, val0, off);
        val1 += __shfl_xor_sync(0xffffffffu, val1, off);
    }
    if ((threadIdx.x & 31) == 0) {
        sred[0][threadIdx.x >> 5] = val0;
        sred[1][threadIdx.x >> 5] = val1;
    }
    __syncthreads();
    if (threadIdx.x == 0) {
        float t0 = 0.0f, t1 = 0.0f;
        #pragma unroll
        for (int w = 0; w < 8; ++w) { t0 += sred[0][w]; t1 += sred[1][w]; }
        out[bi0] = q[bi0] + t0;
        out[bi1] = q[bi1] + t1;
    }
}

// ---------------------------------------------------------------------------
// Launch. Inputs (metadata order): h, e, x, q, mask, W1, b1, W2, b2, W3, b3.
// ---------------------------------------------------------------------------
extern "C" void kernel_launch(void* const* d_in, const int* in_sizes, int n_in,
                              void* d_out, int out_size)
{
    const float* h    = (const float*)d_in[0];
    const float* e    = (const float*)d_in[1];
    const float* x    = (const float*)d_in[2];
    const float* q    = (const float*)d_in[3];
    const float* mask = (const float*)d_in[4];
    const float* W1   = (const float*)d_in[5];
    const float* b1   = (const float*)d_in[6];
    const float* W2   = (const float*)d_in[7];
    const float* b2   = (const float*)d_in[8];
    const float* W3   = (const float*)d_in[9];
    // d_in[10] = b3: cancels in elec_ij - elec_ji.
    float* out = (float*)d_out;

    atom_proj_kernel<<<(NATOMS * (H1C / 2) + 255) / 256, 256>>>(h, x, q, W1, b1);
    pair_kernel<<<NATOMS / 2, 256>>>(e, mask, q, W1, W2, b2, W3, out);
}

// round 11
// speedup vs baseline: 1.6312x; 1.0661x over previous
#include <cuda_runtime.h>

// EPN_layer: antisymmetric pairwise-MLP charge update.
// B=8, N=256, DH=32, DX=3, DQ=1, DE=8, H1=H2=32, DIN=80.
//
// Factorization (layer1 splits by input blocks):
//   A*[a] = inp_atom[a] @ W1[0:36] + b1,  Bt[a] = inp_atom[a] @ W1[36:72]
//   E[i,j] = e[i,j] @ W1[72:80]   (shared by both directions)
//   z1_ij = relu(A*_i + Bt_j + E), z1_ji = relu(A*_j + Bt_i + E); b3 cancels.
//
// R10 = R9's three-port weight split with the even-row indexing bug fixed and
// constant loads made robust (float4-typed __constant__ arrays -> LDC.128):
//   * W2 even-m rows, E-projection weights, b2, W3 -> constant port
//   * W2 odd-m rows -> shared memory (LDS.128)
//   * ab / e / mask data streams -> L1
// Port budget/thread: LDC ~152 (~18us), L1 ~210 wf (~12us), fma ~1300 (~38us)
// -> fma-bound.

#define BB 8
#define NN 256
#define H1C 32
#define H2C 32
#define DEC 8
#define NATOMS (BB * NN)   // 2048

// Per-atom projections packed by k-pair: g_AB4[kk*NATOMS+atom] =
//   (A[2kk], Bt[2kk], A[2kk+1], Bt[2kk+1])
__device__ float4 g_AB4[(H1C / 2) * NATOMS];

// Grid-constant weights (filled by async D2D copies in kernel_launch).
// float4-typed so reads compile to LDC.128 on the constant port.
__constant__ float4 cW1c4[DEC * H1C / 4];   // W1 rows 72..79, [m*8 + f4]
__constant__ float4 cW2v4[H1C * H2C / 4];   // [m*8 + t], floats m*32+4t..+3
__constant__ float  cB2[H2C];
__constant__ float  cW3[H2C];

typedef unsigned long long u64;

__device__ __forceinline__ u64 dup2(float w) {
    u64 r; asm("mov.b64 %0, {%1, %1};" : "=l"(r) : "f"(w)); return r;
}
__device__ __forceinline__ u64 pk2(float lo, float hi) {
    u64 r; asm("mov.b64 %0, {%1, %2};" : "=l"(r) : "f"(lo), "f"(hi)); return r;
}
__device__ __forceinline__ void upk2(float& lo, float& hi, u64 v) {
    asm("mov.b64 {%0, %1}, %2;" : "=f"(lo), "=f"(hi) : "l"(v));
}
__device__ __forceinline__ u64 fma2(u64 a, u64 b, u64 c) {
    u64 d; asm("fma.rn.f32x2 %0, %1, %2, %3;" : "=l"(d) : "l"(a), "l"(b), "l"(c));
    return d;
}
// float4 (already in registers) viewed as two packed-f32x2 operands.
__device__ __forceinline__ ulonglong2 f4u2(float4 f) {
    ulonglong2 r; r.x = pk2(f.x, f.y); r.y = pk2(f.z, f.w); return r;
}

// ---------------------------------------------------------------------------
// Phase 0: per-atom projections. Thread = (atom, k-pair).
// ---------------------------------------------------------------------------
__global__ void atom_proj_kernel(const float* __restrict__ h,
                                 const float* __restrict__ x,
                                 const float* __restrict__ q,
                                 const float* __restrict__ W1,
                                 const float* __restrict__ b1)
{
    int id = blockIdx.x * blockDim.x + threadIdx.x;   // atom*16 + kk
    if (id >= NATOMS * (H1C / 2)) return;
    int kk   = id & 15;
    int atom = id >> 4;
    int k0 = 2 * kk, k1 = k0 + 1;

    float a0 = b1[k0], a1 = b1[k1];
    float t0 = 0.0f,   t1 = 0.0f;
    #pragma unroll
    for (int f = 0; f < 3; ++f) {
        float xv = x[atom * 3 + f];
        a0 = fmaf(xv, W1[f * H1C + k0],        a0);
        a1 = fmaf(xv, W1[f * H1C + k1],        a1);
        t0 = fmaf(xv, W1[(36 + f) * H1C + k0], t0);
        t1 = fmaf(xv, W1[(36 + f) * H1C + k1], t1);
    }
    #pragma unroll
    for (int f = 0; f < 32; ++f) {
        float hv = h[atom * 32 + f];
        a0 = fmaf(hv, W1[(3 + f) * H1C + k0],  a0);
        a1 = fmaf(hv, W1[(3 + f) * H1C + k1],  a1);
        t0 = fmaf(hv, W1[(39 + f) * H1C + k0], t0);
        t1 = fmaf(hv, W1[(39 + f) * H1C + k1], t1);
    }
    float qv = q[atom];
    a0 = fmaf(qv, W1[35 * H1C + k0], a0);
    a1 = fmaf(qv, W1[35 * H1C + k1], a1);
    t0 = fmaf(qv, W1[71 * H1C + k0], t0);
    t1 = fmaf(qv, W1[71 * H1C + k1], t1);

    g_AB4[kk * NATOMS + atom] = make_float4(a0, t0, a1, t1);
}

// ---------------------------------------------------------------------------
// Phase 1: pair kernel. Block = (b,i); thread = j; 2 MLP evals (ij, ji).
// ---------------------------------------------------------------------------
__global__ __launch_bounds__(256, 2)
void pair_kernel(const float* __restrict__ e,
                 const float* __restrict__ mask,
                 const float* __restrict__ q,
                 float* __restrict__ out)
{
    __shared__ alignas(16) float sW2o[H1C / 2][H2C];  // odd-m rows of W2
    __shared__ float sAi[H1C];
    __shared__ float sBi[H1C];
    __shared__ float sred[8];

    const int bi = blockIdx.x;             // b*256 + i
    const int j  = threadIdx.x;
    const int base = bi & ~(NN - 1);       // b*256

    // ---- cooperative staging: odd W2 rows to smem, i-row A/B ----
    #pragma unroll
    for (int t = 0; t < 2; ++t) {
        int idx = threadIdx.x + t * 256;   // 512 = 16 rows x 32
        int mo = idx >> 5;                 // odd row m = 2*mo+1
        int k  = idx & 31;
        const float* cw2 = reinterpret_cast<const float*>(cW2v4);
        sW2o[mo][k] = cw2[(2 * mo + 1) * H2C + k];
    }
    if (threadIdx.x < H1C / 2) {
        float4 f0 = g_AB4[threadIdx.x * NATOMS + bi];
        sAi[2 * threadIdx.x]     = f0.x;
        sBi[2 * threadIdx.x]     = f0.y;
        sAi[2 * threadIdx.x + 1] = f0.z;
        sBi[2 * threadIdx.x + 1] = f0.w;
    }
    __syncthreads();

    // ---- per-pair inputs ----
    const float4* ep = reinterpret_cast<const float4*>(e + ((size_t)bi * NN + j) * DEC);
    float4 e0 = ep[0], e1 = ep[1];
    float ev[8] = {e0.x, e0.y, e0.z, e0.w, e1.x, e1.y, e1.z, e1.w};

    float emax = ev[0];
    #pragma unroll
    for (int m = 1; m < 8; ++m) emax = fmaxf(emax, ev[m]);
    const float mval  = mask[(size_t)bi * NN + j];
    const float scale = (emax > 1e-5f) ? 0.5f * mval : 0.0f;

    // ---- E = e @ W1c, packed over consecutive k-pairs (constant port) ----
    u64 Epk[H1C / 2];
    #pragma unroll
    for (int kk = 0; kk < 16; ++kk) Epk[kk] = 0ull;
    #pragma unroll
    for (int m = 0; m < 8; ++m) {
        u64 em2 = dup2(ev[m]);
        #pragma unroll
        for (int f4 = 0; f4 < 8; ++f4) {
            ulonglong2 w = f4u2(cW1c4[m * 8 + f4]);   // LDC.128
            Epk[2 * f4]     = fma2(em2, w.x, Epk[2 * f4]);
            Epk[2 * f4 + 1] = fma2(em2, w.y, Epk[2 * f4 + 1]);
        }
    }

    // ---- z1 both directions (smem i-row + coalesced float4 j loads) ----
    float z_ij[H1C], z_ji[H1C];
    #pragma unroll
    for (int kk = 0; kk < 16; ++kk) {
        int k0 = 2 * kk, k1 = k0 + 1;
        float E0, E1; upk2(E0, E1, Epk[kk]);
        float4 ab = __ldg(&g_AB4[kk * NATOMS + base + j]);
        z_ij[k0] = fmaxf(sAi[k0] + ab.y + E0, 0.0f);
        z_ji[k0] = fmaxf(ab.x + sBi[k0] + E0, 0.0f);
        z_ij[k1] = fmaxf(sAi[k1] + ab.w + E1, 0.0f);
        z_ji[k1] = fmaxf(ab.z + sBi[k1] + E1, 0.0f);
    }

    // ---- layers 2+3: k in two halves; W2 even rows via constant port,
    //      odd rows via smem; both directions share each weight fetch.
    //      Weight chunk t covers floats m*32 + half*16 + 4t .. +3,
    //      i.e. k-pairs (2t, 2t+1) of this half. ----
    float s_ij = 0.0f, s_ji = 0.0f;
    #pragma unroll
    for (int half = 0; half < 2; ++half) {
        u64 accI[8], accJ[8];
        #pragma unroll
        for (int kk = 0; kk < 8; ++kk) {
            int k0 = half * 16 + 2 * kk;
            u64 bv = pk2(cB2[k0], cB2[k0 + 1]);
            accI[kk] = bv; accJ[kk] = bv;
        }

        #pragma unroll
        for (int m = 0; m < H1C; ++m) {
            u64 zi2 = dup2(z_ij[m]);
            u64 zj2 = dup2(z_ji[m]);
            ulonglong2 w0, w1, w2, w3;     // 4 x (2 k-pairs each)
            if (m & 1) {
                const ulonglong2* wr =
                    reinterpret_cast<const ulonglong2*>(&sW2o[m >> 1][half * 16]);
                w0 = wr[0]; w1 = wr[1]; w2 = wr[2]; w3 = wr[3];   // LDS.128 x4
            } else {
                w0 = f4u2(cW2v4[m * 8 + half * 4 + 0]);           // LDC.128 x4
                w1 = f4u2(cW2v4[m * 8 + half * 4 + 1]);
                w2 = f4u2(cW2v4[m * 8 + half * 4 + 2]);
                w3 = f4u2(cW2v4[m * 8 + half * 4 + 3]);
            }
            accI[0] = fma2(zi2, w0.x, accI[0]);
            accJ[0] = fma2(zj2, w0.x, accJ[0]);
            accI[1] = fma2(zi2, w0.y, accI[1]);
            accJ[1] = fma2(zj2, w0.y, accJ[1]);
            accI[2] = fma2(zi2, w1.x, accI[2]);
            accJ[2] = fma2(zj2, w1.x, accJ[2]);
            accI[3] = fma2(zi2, w1.y, accI[3]);
            accJ[3] = fma2(zj2, w1.y, accJ[3]);
            accI[4] = fma2(zi2, w2.x, accI[4]);
            accJ[4] = fma2(zj2, w2.x, accJ[4]);
            accI[5] = fma2(zi2, w2.y, accI[5]);
            accJ[5] = fma2(zj2, w2.y, accJ[5]);
            accI[6] = fma2(zi2, w3.x, accI[6]);
            accJ[6] = fma2(zj2, w3.x, accJ[6]);
            accI[7] = fma2(zi2, w3.y, accI[7]);
            accJ[7] = fma2(zj2, w3.y, accJ[7]);
        }

        #pragma unroll
        for (int kk = 0; kk < 8; ++kk) {
            int k0 = half * 16 + 2 * kk;
            float w0 = cW3[k0], w1 = cW3[k0 + 1];
            float a, b;
            upk2(a, b, accI[kk]);
            s_ij = fmaf(fmaxf(a, 0.0f), w0, s_ij);
            s_ij = fmaf(fmaxf(b, 0.0f), w1, s_ij);
            upk2(a, b, accJ[kk]);
            s_ji = fmaf(fmaxf(a, 0.0f), w0, s_ji);
            s_ji = fmaf(fmaxf(b, 0.0f), w1, s_ji);
        }
    }
    float val = scale * (s_ij - s_ji);   // b3 cancels

    // ---- block reduction over j ----
    #pragma unroll
    for (int off = 16; off > 0; off >>= 1)
        val += __shfl_xor_sync(0xffffffffu, val, off);
    if ((threadIdx.x & 31) == 0) sred[threadIdx.x >> 5] = val;
    __syncthreads();
    if (threadIdx.x == 0) {
        float t = 0.0f;
        #pragma unroll
        for (int w = 0; w < 8; ++w) t += sred[w];
        out[bi] = q[bi] + t;
    }
}

// ---------------------------------------------------------------------------
// Launch. Inputs (metadata order): h, e, x, q, mask, W1, b1, W2, b2, W3, b3.
// Async D2D copies into __constant__ are stream-ordered, graph-capturable.
// ---------------------------------------------------------------------------
extern "C" void kernel_launch(void* const* d_in, const int* in_sizes, int n_in,
                              void* d_out, int out_size)
{
    const float* h    = (const float*)d_in[0];
    const float* e    = (const float*)d_in[1];
    const float* x    = (const float*)d_in[2];
    const float* q    = (const float*)d_in[3];
    const float* mask = (const float*)d_in[4];
    const float* W1   = (const float*)d_in[5];
    const float* b1   = (const float*)d_in[6];
    const float* W2   = (const float*)d_in[7];
    const float* b2   = (const float*)d_in[8];
    const float* W3   = (const float*)d_in[9];
    // d_in[10] = b3: cancels in elec_ij - elec_ji.
    float* out = (float*)d_out;

    void *pW1c, *pW2, *pB2, *pW3;
    cudaGetSymbolAddress(&pW1c, cW1c4);
    cudaGetSymbolAddress(&pW2,  cW2v4);
    cudaGetSymbolAddress(&pB2,  cB2);
    cudaGetSymbolAddress(&pW3,  cW3);
    cudaMemcpyAsync(pW1c, W1 + 72 * H1C, DEC * H1C * sizeof(float),
                    cudaMemcpyDeviceToDevice);
    cudaMemcpyAsync(pW2,  W2, H1C * H2C * sizeof(float), cudaMemcpyDeviceToDevice);
    cudaMemcpyAsync(pB2,  b2, H2C * sizeof(float),       cudaMemcpyDeviceToDevice);
    cudaMemcpyAsync(pW3,  W3, H2C * sizeof(float),       cudaMemcpyDeviceToDevice);

    atom_proj_kernel<<<(NATOMS * (H1C / 2) + 255) / 256, 256>>>(h, x, q, W1, b1);
    pair_kernel<<<NATOMS, 256>>>(e, mask, q, out);
}

// round 12
// speedup vs baseline: 1.6870x; 1.0342x over previous
#include <cuda_runtime.h>

// EPN_layer: antisymmetric pairwise-MLP charge update.
// B=8, N=256, DH=32, DX=3, DQ=1, DE=8, H1=H2=32, DIN=80.
//
// Factorization (layer1 splits by input blocks):
//   A*[a] = inp_atom[a] @ W1[0:36] + b1,  Bt[a] = inp_atom[a] @ W1[36:72]
//   E[i,j] = e[i,j] @ W1[72:80]   (shared by both directions)
//   z1_ij = relu(A*_i + Bt_j + E), z1_ji = relu(A*_j + Bt_i + E); b3 cancels.
//
// R11 = R10 (three-port weight split: W2-even/E-proj/b2/W3 on the constant
// port, W2-odd in smem, data streams in L1) + overhead elimination:
//  * PERSISTENT pair kernel: grid=296 (=2x148, the reg-limited occupancy);
//    each block loops rows bi += 296. One wave (was 6.92) -> no wave
//    transitions; weight staging amortized 2048 -> 296 times.
//  * Constants packed into ONE __constant__ array filled by a gather kernel
//    + a single D2D memcpy (graph nodes 6 -> 4).

#define BB 8
#define NN 256
#define H1C 32
#define H2C 32
#define DEC 8
#define NATOMS (BB * NN)   // 2048
#define PGRID 296          // persistent grid: 2 blocks x 148 SMs

// Per-atom projections packed by k-pair: g_AB4[kk*NATOMS+atom] =
//   (A[2kk], Bt[2kk], A[2kk+1], Bt[2kk+1])
__device__ float4 g_AB4[(H1C / 2) * NATOMS];

// Packed constant block (filled via g_stage + one memcpy):
//   [0,256)    W1 rows 72..79 (e-projection)     float4 idx: m*8+f4
//   [256,1280) W2 [m][k]                          float4 idx: 64+m*8+t
//   [1280,1312) b2
//   [1312,1344) W3
#define CW2_F 256
#define CB2_F 1280
#define CW3_F 1312
#define CTOT  1344
__device__ alignas(16) float g_stage[CTOT];
__constant__ alignas(16) float cAll[CTOT];

typedef unsigned long long u64;

__device__ __forceinline__ u64 dup2(float w) {
    u64 r; asm("mov.b64 %0, {%1, %1};" : "=l"(r) : "f"(w)); return r;
}
__device__ __forceinline__ u64 pk2(float lo, float hi) {
    u64 r; asm("mov.b64 %0, {%1, %2};" : "=l"(r) : "f"(lo), "f"(hi)); return r;
}
__device__ __forceinline__ void upk2(float& lo, float& hi, u64 v) {
    asm("mov.b64 {%0, %1}, %2;" : "=f"(lo), "=f"(hi) : "l"(v));
}
__device__ __forceinline__ u64 fma2(u64 a, u64 b, u64 c) {
    u64 d; asm("fma.rn.f32x2 %0, %1, %2, %3;" : "=l"(d) : "l"(a), "l"(b), "l"(c));
    return d;
}
// float4 (in registers) viewed as two packed-f32x2 operands.
__device__ __forceinline__ ulonglong2 f4u2(float4 f) {
    ulonglong2 r; r.x = pk2(f.x, f.y); r.y = pk2(f.z, f.w); return r;
}

// ---------------------------------------------------------------------------
// Phase -1: gather all constant-bound weights into one contiguous staging
// buffer (single D2D memcpy to cAll afterwards).
// ---------------------------------------------------------------------------
__global__ void gather_weights(const float* __restrict__ W1,
                               const float* __restrict__ W2,
                               const float* __restrict__ b2,
                               const float* __restrict__ W3)
{
    int t = blockIdx.x * blockDim.x + threadIdx.x;
    if (t < CW2_F)          g_stage[t] = W1[72 * H1C + t];
    else if (t < CB2_F)     g_stage[t] = W2[t - CW2_F];
    else if (t < CW3_F)     g_stage[t] = b2[t - CB2_F];
    else if (t < CTOT)      g_stage[t] = W3[t - CW3_F];
}

// ---------------------------------------------------------------------------
// Phase 0: per-atom projections. Thread = (atom, k-pair).
// ---------------------------------------------------------------------------
__global__ void atom_proj_kernel(const float* __restrict__ h,
                                 const float* __restrict__ x,
                                 const float* __restrict__ q,
                                 const float* __restrict__ W1,
                                 const float* __restrict__ b1)
{
    int id = blockIdx.x * blockDim.x + threadIdx.x;   // atom*16 + kk
    if (id >= NATOMS * (H1C / 2)) return;
    int kk   = id & 15;
    int atom = id >> 4;
    int k0 = 2 * kk, k1 = k0 + 1;

    float a0 = b1[k0], a1 = b1[k1];
    float t0 = 0.0f,   t1 = 0.0f;
    #pragma unroll
    for (int f = 0; f < 3; ++f) {
        float xv = x[atom * 3 + f];
        a0 = fmaf(xv, W1[f * H1C + k0],        a0);
        a1 = fmaf(xv, W1[f * H1C + k1],        a1);
        t0 = fmaf(xv, W1[(36 + f) * H1C + k0], t0);
        t1 = fmaf(xv, W1[(36 + f) * H1C + k1], t1);
    }
    #pragma unroll
    for (int f = 0; f < 32; ++f) {
        float hv = h[atom * 32 + f];
        a0 = fmaf(hv, W1[(3 + f) * H1C + k0],  a0);
        a1 = fmaf(hv, W1[(3 + f) * H1C + k1],  a1);
        t0 = fmaf(hv, W1[(39 + f) * H1C + k0], t0);
        t1 = fmaf(hv, W1[(39 + f) * H1C + k1], t1);
    }
    float qv = q[atom];
    a0 = fmaf(qv, W1[35 * H1C + k0], a0);
    a1 = fmaf(qv, W1[35 * H1C + k1], a1);
    t0 = fmaf(qv, W1[71 * H1C + k0], t0);
    t1 = fmaf(qv, W1[71 * H1C + k1], t1);

    g_AB4[kk * NATOMS + atom] = make_float4(a0, t0, a1, t1);
}

// ---------------------------------------------------------------------------
// Phase 1: persistent pair kernel. Block loops rows bi += PGRID; thread = j.
// ---------------------------------------------------------------------------
__global__ __launch_bounds__(256, 2)
void pair_kernel(const float* __restrict__ e,
                 const float* __restrict__ mask,
                 const float* __restrict__ q,
                 float* __restrict__ out)
{
    __shared__ alignas(16) float sW2o[H1C / 2][H2C];  // odd-m rows of W2
    __shared__ float sAi[H1C];
    __shared__ float sBi[H1C];
    __shared__ float sred[8];

    const int j = threadIdx.x;
    const float4* __restrict__ c4 = reinterpret_cast<const float4*>(cAll);

    // ---- one-time staging: odd W2 rows constant -> smem ----
    #pragma unroll
    for (int t = 0; t < 2; ++t) {
        int idx = threadIdx.x + t * 256;   // 512 = 16 rows x 32
        int mo = idx >> 5;                 // odd row m = 2*mo+1
        int k  = idx & 31;
        sW2o[mo][k] = cAll[CW2_F + (2 * mo + 1) * H2C + k];
    }

    for (int bi = blockIdx.x; bi < NATOMS; bi += PGRID) {
        const int base = bi & ~(NN - 1);   // b*256

        // per-row staging: i-row A/B (first iter also covered by this sync)
        if (threadIdx.x < H1C / 2) {
            float4 f0 = g_AB4[threadIdx.x * NATOMS + bi];
            sAi[2 * threadIdx.x]     = f0.x;
            sBi[2 * threadIdx.x]     = f0.y;
            sAi[2 * threadIdx.x + 1] = f0.z;
            sBi[2 * threadIdx.x + 1] = f0.w;
        }
        __syncthreads();

        // ---- per-pair inputs ----
        const float4* ep =
            reinterpret_cast<const float4*>(e + ((size_t)bi * NN + j) * DEC);
        float4 e0 = ep[0], e1 = ep[1];
        float ev[8] = {e0.x, e0.y, e0.z, e0.w, e1.x, e1.y, e1.z, e1.w};

        float emax = ev[0];
        #pragma unroll
        for (int m = 1; m < 8; ++m) emax = fmaxf(emax, ev[m]);
        const float mval  = mask[(size_t)bi * NN + j];
        const float scale = (emax > 1e-5f) ? 0.5f * mval : 0.0f;

        // ---- E = e @ W1c, packed over consecutive k-pairs (constant port) ----
        u64 Epk[H1C / 2];
        #pragma unroll
        for (int kk = 0; kk < 16; ++kk) Epk[kk] = 0ull;
        #pragma unroll
        for (int m = 0; m < 8; ++m) {
            u64 em2 = dup2(ev[m]);
            #pragma unroll
            for (int f4 = 0; f4 < 8; ++f4) {
                ulonglong2 w = f4u2(c4[m * 8 + f4]);     // LDC.128
                Epk[2 * f4]     = fma2(em2, w.x, Epk[2 * f4]);
                Epk[2 * f4 + 1] = fma2(em2, w.y, Epk[2 * f4 + 1]);
            }
        }

        // ---- z1 both directions (smem i-row + coalesced float4 j loads) ----
        float z_ij[H1C], z_ji[H1C];
        #pragma unroll
        for (int kk = 0; kk < 16; ++kk) {
            int k0 = 2 * kk, k1 = k0 + 1;
            float E0, E1; upk2(E0, E1, Epk[kk]);
            float4 ab = __ldg(&g_AB4[kk * NATOMS + base + j]);
            z_ij[k0] = fmaxf(sAi[k0] + ab.y + E0, 0.0f);
            z_ji[k0] = fmaxf(ab.x + sBi[k0] + E0, 0.0f);
            z_ij[k1] = fmaxf(sAi[k1] + ab.w + E1, 0.0f);
            z_ji[k1] = fmaxf(ab.z + sBi[k1] + E1, 0.0f);
        }

        // ---- layers 2+3: k in two halves; W2 even rows via constant port,
        //      odd rows via smem; chunk t covers floats m*32+half*16+4t..+3
        //      = k-pairs (2t, 2t+1) of this half. ----
        float s_ij = 0.0f, s_ji = 0.0f;
        #pragma unroll
        for (int half = 0; half < 2; ++half) {
            u64 accI[8], accJ[8];
            #pragma unroll
            for (int kk = 0; kk < 8; ++kk) {
                int k0 = half * 16 + 2 * kk;
                u64 bv = pk2(cAll[CB2_F + k0], cAll[CB2_F + k0 + 1]);
                accI[kk] = bv; accJ[kk] = bv;
            }

            #pragma unroll
            for (int m = 0; m < H1C; ++m) {
                u64 zi2 = dup2(z_ij[m]);
                u64 zj2 = dup2(z_ji[m]);
                ulonglong2 w0, w1, w2, w3;   // 4 x (2 k-pairs each)
                if (m & 1) {
                    const ulonglong2* wr = reinterpret_cast<const ulonglong2*>(
                        &sW2o[m >> 1][half * 16]);
                    w0 = wr[0]; w1 = wr[1]; w2 = wr[2]; w3 = wr[3];  // LDS.128
                } else {
                    w0 = f4u2(c4[64 + m * 8 + half * 4 + 0]);        // LDC.128
                    w1 = f4u2(c4[64 + m * 8 + half * 4 + 1]);
                    w2 = f4u2(c4[64 + m * 8 + half * 4 + 2]);
                    w3 = f4u2(c4[64 + m * 8 + half * 4 + 3]);
                }
                accI[0] = fma2(zi2, w0.x, accI[0]);
                accJ[0] = fma2(zj2, w0.x, accJ[0]);
                accI[1] = fma2(zi2, w0.y, accI[1]);
                accJ[1] = fma2(zj2, w0.y, accJ[1]);
                accI[2] = fma2(zi2, w1.x, accI[2]);
                accJ[2] = fma2(zj2, w1.x, accJ[2]);
                accI[3] = fma2(zi2, w1.y, accI[3]);
                accJ[3] = fma2(zj2, w1.y, accJ[3]);
                accI[4] = fma2(zi2, w2.x, accI[4]);
                accJ[4] = fma2(zj2, w2.x, accJ[4]);
                accI[5] = fma2(zi2, w2.y, accI[5]);
                accJ[5] = fma2(zj2, w2.y, accJ[5]);
                accI[6] = fma2(zi2, w3.x, accI[6]);
                accJ[6] = fma2(zj2, w3.x, accJ[6]);
                accI[7] = fma2(zi2, w3.y, accI[7]);
                accJ[7] = fma2(zj2, w3.y, accJ[7]);
            }

            #pragma unroll
            for (int kk = 0; kk < 8; ++kk) {
                int k0 = half * 16 + 2 * kk;
                float w0 = cAll[CW3_F + k0], w1 = cAll[CW3_F + k0 + 1];
                float a, b;
                upk2(a, b, accI[kk]);
                s_ij = fmaf(fmaxf(a, 0.0f), w0, s_ij);
                s_ij = fmaf(fmaxf(b, 0.0f), w1, s_ij);
                upk2(a, b, accJ[kk]);
                s_ji = fmaf(fmaxf(a, 0.0f), w0, s_ji);
                s_ji = fmaf(fmaxf(b, 0.0f), w1, s_ji);
            }
        }
        float val = scale * (s_ij - s_ji);   // b3 cancels

        // ---- block reduction over j ----
        #pragma unroll
        for (int off = 16; off > 0; off >>= 1)
            val += __shfl_xor_sync(0xffffffffu, val, off);
        if ((threadIdx.x & 31) == 0) sred[threadIdx.x >> 5] = val;
        __syncthreads();
        if (threadIdx.x == 0) {
            float t = 0.0f;
            #pragma unroll
            for (int w = 0; w < 8; ++w) t += sred[w];
            out[bi] = q[bi] + t;
        }
        // next iteration's sAi write is guarded by its own __syncthreads;
        // sred reuse is guarded because lane0 writes happen after that sync.
    }
}

// ---------------------------------------------------------------------------
// Launch. Inputs (metadata order): h, e, x, q, mask, W1, b1, W2, b2, W3, b3.
// Graph: gather -> memcpy(cAll) -> atom_proj -> pair (4 nodes).
// ---------------------------------------------------------------------------
extern "C" void kernel_launch(void* const* d_in, const int* in_sizes, int n_in,
                              void* d_out, int out_size)
{
    const float* h    = (const float*)d_in[0];
    const float* e    = (const float*)d_in[1];
    const float* x    = (const float*)d_in[2];
    const float* q    = (const float*)d_in[3];
    const float* mask = (const float*)d_in[4];
    const float* W1   = (const float*)d_in[5];
    const float* b1   = (const float*)d_in[6];
    const float* W2   = (const float*)d_in[7];
    const float* b2   = (const float*)d_in[8];
    const float* W3   = (const float*)d_in[9];
    // d_in[10] = b3: cancels in elec_ij - elec_ji.
    float* out = (float*)d_out;

    gather_weights<<<(CTOT + 255) / 256, 256>>>(W1, W2, b2, W3);

    void *pAll, *pStage;
    cudaGetSymbolAddress(&pAll,   cAll);
    cudaGetSymbolAddress(&pStage, g_stage);
    cudaMemcpyAsync(pAll, pStage, CTOT * sizeof(float), cudaMemcpyDeviceToDevice);

    atom_proj_kernel<<<(NATOMS * (H1C / 2) + 255) / 256, 256>>>(h, x, q, W1, b1);
    pair_kernel<<<PGRID, 256>>>(e, mask, q, out);
}